// round 16
// baseline (speedup 1.0000x reference)
#include <cuda_runtime.h>
#include <cuda_bf16.h>
#include <math.h>
#include <stdint.h>

// Problem dims
#define Bn 32
#define Tn 64
#define In 300
#define Hn 168
#define Cn 168
#define Sn 512
#define Vn 50257
#define G4 672      // 4*H
#define ICn 468     // I + C

// Cluster recurrence dims
#define NR 4        // CTAs per batch (cluster size)
#define UPC 42      // hidden units per CTA
#define HLP 44      // padded group width (mult of 4)
#define JLP 176     // 4*HLP packed gate rows per CTA
#define SLOC 128    // Sn / NR
#define RTHREADS 512
#define DYNSM_FLOATS (2 * SLOC * Hn)          // seqp slice + ctx slice
#define DYNSM_BYTES  (DYNSM_FLOATS * 4)       // 172032 B

// Decode GEMM dims
#define KP 176
#define NPAD 50304
#define NTILES_N 393
#define NTILES_M 16
#define KCHUNKS 11

// ---------------- device scratch ----------------
__device__ __align__(16) float g_seqp[Bn * Sn * Hn];
__device__ __align__(16) float g_xwp[Bn * Tn * NR * JLP];   // packed per-rank xw (pads stay 0)
__device__ __align__(16) float g_Wp[NR * Hn * JLP];         // W_hh packed  [r][k][jl]
__device__ __align__(16) float g_WC[NR * Cn * JLP];         // W_ih_ctx packed [r][c][jl]
__device__ __align__(16) float g_WsT[Hn * Cn];
__device__ __align__(16) float g_bias[G4];
__device__ __align__(16) float g_hs[Bn * Tn * Hn];
__device__ __align__(16) __nv_bfloat16 g_Ahi[Bn * Tn * KP];
__device__ __align__(16) __nv_bfloat16 g_Alo[Bn * Tn * KP];
__device__ __align__(16) __nv_bfloat16 g_Bhi[(long)NPAD * KP];
__device__ __align__(16) __nv_bfloat16 g_Blo[(long)NPAD * KP];

// ---------------- helpers ----------------
__device__ __forceinline__ float tanh_fast(float x) {
    float y; asm("tanh.approx.f32 %0, %1;" : "=f"(y) : "f"(x)); return y;
}
__device__ __forceinline__ float sigmoidf(float x) { return 1.0f / (1.0f + expf(-x)); }

__device__ __forceinline__ uint32_t smem_u32(const void* p) {
    uint32_t a;
    asm("{ .reg .u64 t; cvta.to.shared.u64 t, %1; cvt.u32.u64 %0, t; }" : "=r"(a) : "l"(p));
    return a;
}
__device__ __forceinline__ uint32_t mapa_u32(uint32_t a, uint32_t rank) {
    uint32_t r;
    asm("mapa.shared::cluster.u32 %0, %1, %2;" : "=r"(r) : "r"(a), "r"(rank));
    return r;
}
__device__ __forceinline__ void st_cluster_f32(uint32_t a, float v) {
    asm volatile("st.shared::cluster.f32 [%0], %1;" :: "r"(a), "f"(v) : "memory");
}
#define CLUSTER_SYNC() do { \
    asm volatile("barrier.cluster.arrive.aligned;" ::: "memory"); \
    asm volatile("barrier.cluster.wait.aligned;" ::: "memory"); } while (0)

__device__ __forceinline__ void ldsm_x4(uint32_t* r, uint32_t addr) {
    asm volatile("ldmatrix.sync.aligned.m8n8.x4.shared.b16 {%0,%1,%2,%3}, [%4];"
                 : "=r"(r[0]), "=r"(r[1]), "=r"(r[2]), "=r"(r[3]) : "r"(addr));
}
__device__ __forceinline__ void mma_bf16(float* c, const uint32_t* a, uint32_t b0, uint32_t b1) {
    asm volatile(
        "mma.sync.aligned.m16n8k16.row.col.f32.bf16.bf16.f32 "
        "{%0,%1,%2,%3}, {%4,%5,%6,%7}, {%8,%9}, {%0,%1,%2,%3};"
        : "+f"(c[0]), "+f"(c[1]), "+f"(c[2]), "+f"(c[3])
        : "r"(a[0]), "r"(a[1]), "r"(a[2]), "r"(a[3]), "r"(b0), "r"(b1));
}

// ---------------- prep: packed weight images + misc ----------------
__global__ void prep_kernel(const float* __restrict__ Whh,
                            const float* __restrict__ Wih,
                            const float* __restrict__ attWs,
                            const float* __restrict__ bih,
                            const float* __restrict__ bhh) {
    int idx = blockIdx.x * blockDim.x + threadIdx.x;
    if (idx < NR * Hn * JLP) {
        int r = idx / (Hn * JLP);
        int rem = idx % (Hn * JLP);
        int k = rem / JLP, jl = rem % JLP;
        int g = jl / HLP, nl = jl % HLP;
        float wv = 0.f, wc = 0.f;
        if (nl < UPC) {
            int j = g * Hn + UPC * r + nl;
            wv = Whh[j * Hn + k];
            wc = Wih[j * ICn + In + k];
        }
        g_Wp[idx] = wv;
        g_WC[idx] = wc;
    }
    if (idx < Hn * Cn) {
        int a = idx / Cn, c = idx % Cn;
        g_WsT[a * Cn + c] = attWs[c * Hn + a];
    }
    if (idx < G4) g_bias[idx] = bih[idx] + bhh[idx];
}

// ---------------- hi/lo bf16 conversion ----------------
__device__ __forceinline__ void conv_hilo_body(const float* __restrict__ src, int nrows_src,
                                               __nv_bfloat16* __restrict__ hi,
                                               __nv_bfloat16* __restrict__ lo,
                                               int nrows_pad) {
    int idx = blockIdx.x * blockDim.x + threadIdx.x;
    int row = idx / (KP / 8);
    int u = idx % (KP / 8);
    if (row >= nrows_pad) return;
    int c0 = u * 8;
    __nv_bfloat16 h8[8], l8[8];
    if (row < nrows_src && c0 < Hn) {
        const float* sp = src + (long)row * Hn + c0;
#pragma unroll
        for (int e = 0; e < 8; e++) {
            float v = sp[e];
            __nv_bfloat16 h = __float2bfloat16(v);
            h8[e] = h;
            l8[e] = __float2bfloat16(v - __bfloat162float(h));
        }
    } else {
#pragma unroll
        for (int e = 0; e < 8; e++) { h8[e] = __float2bfloat16(0.f); l8[e] = h8[e]; }
    }
    *(uint4*)(hi + (long)row * KP + c0) = *(uint4*)h8;
    *(uint4*)(lo + (long)row * KP + c0) = *(uint4*)l8;
}
__global__ __launch_bounds__(256) void conv_A_kernel() {
    conv_hilo_body(g_hs, Bn * Tn, g_Ahi, g_Alo, Bn * Tn);
}
__global__ __launch_bounds__(256) void conv_B_kernel(const float* __restrict__ Wdec) {
    conv_hilo_body(Wdec, Vn, g_Bhi, g_Blo, NPAD);
}

// ---------------- decode: bf16 hi/lo mma.sync, pipelined loads + coalesced epilogue ----------------
#define SSTRIDE 24
__global__ __launch_bounds__(256) void decode_mma_kernel(float* __restrict__ out) {
    // single smem buffer: 4 bf16 tiles (24576 B) during mainloop; float staging (16512 B) in epilogue
    __shared__ __align__(16) unsigned char smbuf[4 * 128 * SSTRIDE * 2];
    __nv_bfloat16* sAh = (__nv_bfloat16*)smbuf;
    __nv_bfloat16* sAl = sAh + 128 * SSTRIDE;
    __nv_bfloat16* sBh = sAl + 128 * SSTRIDE;
    __nv_bfloat16* sBl = sBh + 128 * SSTRIDE;

    int tid = threadIdx.x;
    int lane = tid & 31;
    int wid = tid >> 5;
    int wm = (wid & 1) * 64;
    int wn = (wid >> 1) * 32;
    int m0 = blockIdx.y * 128;
    int n0 = blockIdx.x * 128;

    float acc[4][4][4];
#pragma unroll
    for (int i = 0; i < 4; i++)
#pragma unroll
        for (int j = 0; j < 4; j++)
#pragma unroll
            for (int e = 0; e < 4; e++) acc[i][j][e] = 0.f;

    int lrow = tid >> 1;
    int lhalf = (tid & 1) * 8;

    uint32_t aAh = smem_u32(sAh + (wm + (lane & 15)) * SSTRIDE + (lane >> 4) * 8);
    uint32_t aAl = smem_u32(sAl + (wm + (lane & 15)) * SSTRIDE + (lane >> 4) * 8);
    int bg = lane >> 3;
    int brow = wn + (bg >> 1) * 8 + (lane & 7);
    int bk = (bg & 1) * 8;
    uint32_t aBh0 = smem_u32(sBh + brow * SSTRIDE + bk);
    uint32_t aBl0 = smem_u32(sBl + brow * SSTRIDE + bk);

    long kaBase = (long)(m0 + lrow) * KP + lhalf;
    long kbBase = (long)(n0 + lrow) * KP + lhalf;

    // prologue: prefetch chunk 0
    uint4 vAh = *(const uint4*)(g_Ahi + kaBase);
    uint4 vAl = *(const uint4*)(g_Alo + kaBase);
    uint4 vBh = *(const uint4*)(g_Bhi + kbBase);
    uint4 vBl = *(const uint4*)(g_Blo + kbBase);

    for (int kc = 0; kc < KCHUNKS; kc++) {
        __syncthreads();
        *(uint4*)(sAh + lrow * SSTRIDE + lhalf) = vAh;
        *(uint4*)(sAl + lrow * SSTRIDE + lhalf) = vAl;
        *(uint4*)(sBh + lrow * SSTRIDE + lhalf) = vBh;
        *(uint4*)(sBl + lrow * SSTRIDE + lhalf) = vBl;
        __syncthreads();

        if (kc + 1 < KCHUNKS) {
            long ka = kaBase + (kc + 1) * 16;
            long kb = kbBase + (kc + 1) * 16;
            vAh = *(const uint4*)(g_Ahi + ka);
            vAl = *(const uint4*)(g_Alo + ka);
            vBh = *(const uint4*)(g_Bhi + kb);
            vBl = *(const uint4*)(g_Blo + kb);
        }

        uint32_t ah[4][4], al[4][4], bh[2][4], bl[2][4];
#pragma unroll
        for (int mi = 0; mi < 4; mi++) {
            ldsm_x4(ah[mi], aAh + mi * 16 * (SSTRIDE * 2));
            ldsm_x4(al[mi], aAl + mi * 16 * (SSTRIDE * 2));
        }
#pragma unroll
        for (int g = 0; g < 2; g++) {
            ldsm_x4(bh[g], aBh0 + g * 16 * (SSTRIDE * 2));
            ldsm_x4(bl[g], aBl0 + g * 16 * (SSTRIDE * 2));
        }

#pragma unroll
        for (int mi = 0; mi < 4; mi++) {
#pragma unroll
            for (int ni = 0; ni < 4; ni++) {
                int g = ni >> 1, sub = (ni & 1) * 2;
                mma_bf16(acc[mi][ni], ah[mi], bh[g][sub], bh[g][sub + 1]);
                mma_bf16(acc[mi][ni], ah[mi], bl[g][sub], bl[g][sub + 1]);
            }
        }
#pragma unroll
        for (int mi = 0; mi < 4; mi++) {
#pragma unroll
            for (int ni = 0; ni < 4; ni++) {
                int g = ni >> 1, sub = (ni & 1) * 2;
                mma_bf16(acc[mi][ni], al[mi], bh[g][sub], bh[g][sub + 1]);
            }
        }
    }

    // ---- epilogue: stage 32-row windows in smem, write coalesced ----
    float* stg = (float*)smbuf;    // [32][129] = 16512 B, reuses tile smem
    __syncthreads();               // all MMAs done reading tiles
    int lrow2 = tid >> 7;          // 0..1
    int lcol = tid & 127;
    int gcol = n0 + lcol;
#pragma unroll
    for (int round = 0; round < 4; round++) {
        if (wm == (round >> 1) * 64) {
            int mibase = (round & 1) * 2;
#pragma unroll
            for (int mi2 = 0; mi2 < 2; mi2++) {
                int mi = mibase + mi2;
                int rloc = mi * 16 + (lane >> 2) - (round & 1) * 32;
#pragma unroll
                for (int ni = 0; ni < 4; ni++) {
                    int cc = wn + (lane & 3) * 2 + ni * 8;
                    stg[rloc * 129 + cc]           = acc[mi][ni][0];
                    stg[rloc * 129 + cc + 1]       = acc[mi][ni][1];
                    stg[(rloc + 8) * 129 + cc]     = acc[mi][ni][2];
                    stg[(rloc + 8) * 129 + cc + 1] = acc[mi][ni][3];
                }
            }
        }
        __syncthreads();
        if (gcol < Vn) {
#pragma unroll
            for (int rr = 0; rr < 32; rr += 2) {
                int row = rr + lrow2;
                out[(long)(m0 + round * 32 + row) * Vn + gcol] = stg[row * 129 + lcol];
            }
        }
        __syncthreads();
    }
}

// ---------------- seqproj SGEMM ----------------
__global__ __launch_bounds__(256) void gemm_seqproj(const float* __restrict__ context,
                                                    const float* __restrict__ attb) {
    const int BM = 64, BN = 128, BK = 8;
    const float* A = context; int lda = Cn;
    const float* Bm = g_WsT;  int ldb = Cn;
    float* D = g_seqp;        int ldd = Hn;
    const int M = Bn * Sn, N = Hn, K = Cn;
    __shared__ float As[BK][BM];
    __shared__ float Bs[BK][BN];
    int bm = blockIdx.y * BM, bn = blockIdx.x * BN;
    int tid = threadIdx.x, tx = tid & 15, ty = tid >> 4;
    float acc[4][8];
#pragma unroll
    for (int i = 0; i < 4; i++)
#pragma unroll
        for (int j = 0; j < 8; j++) acc[i][j] = 0.0f;
    for (int k0 = 0; k0 < K; k0 += BK) {
#pragma unroll
        for (int e = 0; e < 2; e++) {
            int q = tid + 256 * e;
            int m = q >> 3, kk = q & 7;
            int gm = bm + m, gk = k0 + kk;
            float v = 0.0f;
            if (gk < K && gm < M) v = A[(long)gm * lda + gk];
            As[kk][m] = v;
        }
#pragma unroll
        for (int e = 0; e < 4; e++) {
            int q = tid + 256 * e;
            int n = q >> 3, kk = q & 7;
            int gn = bn + n, gk = k0 + kk;
            float v = 0.0f;
            if (gk < K && gn < N) v = Bm[(long)gn * ldb + gk];
            Bs[kk][n] = v;
        }
        __syncthreads();
#pragma unroll
        for (int kk = 0; kk < BK; kk++) {
            float4 a4 = *(const float4*)&As[kk][ty * 4];
            float4 b0 = *(const float4*)&Bs[kk][tx * 8];
            float4 b1 = *(const float4*)&Bs[kk][tx * 8 + 4];
            float av[4] = {a4.x, a4.y, a4.z, a4.w};
            float bv[8] = {b0.x, b0.y, b0.z, b0.w, b1.x, b1.y, b1.z, b1.w};
#pragma unroll
            for (int i = 0; i < 4; i++)
#pragma unroll
                for (int j = 0; j < 8; j++)
                    acc[i][j] = fmaf(av[i], bv[j], acc[i][j]);
        }
        __syncthreads();
    }
#pragma unroll
    for (int i = 0; i < 4; i++) {
        int gm = bm + ty * 4 + i;
        if (gm >= M) continue;
#pragma unroll
        for (int j = 0; j < 8; j++) {
            int gn = bn + tx * 8 + j;
            if (gn < N) D[(long)gm * ldd + gn] = acc[i][j] + attb[gn];
        }
    }
}

// ---------------- xw GEMM with fused packed epilogue ----------------
__global__ __launch_bounds__(256) void gemm_xw_packed(const float* __restrict__ x,
                                                      const float* __restrict__ Wih) {
    const int BM = 64, BN = 128, BK = 8;
    const float* A = x;      int lda = In;
    const float* Bm = Wih;   int ldb = ICn;
    const int M = Bn * Tn, N = G4, K = In;
    __shared__ float As[BK][BM];
    __shared__ float Bs[BK][BN];
    int bm = blockIdx.y * BM, bn = blockIdx.x * BN;
    int tid = threadIdx.x, tx = tid & 15, ty = tid >> 4;
    float acc[4][8];
#pragma unroll
    for (int i = 0; i < 4; i++)
#pragma unroll
        for (int j = 0; j < 8; j++) acc[i][j] = 0.0f;
    for (int k0 = 0; k0 < K; k0 += BK) {
#pragma unroll
        for (int e = 0; e < 2; e++) {
            int q = tid + 256 * e;
            int m = q >> 3, kk = q & 7;
            int gm = bm + m, gk = k0 + kk;
            float v = 0.0f;
            if (gk < K && gm < M) v = A[(long)gm * lda + gk];
            As[kk][m] = v;
        }
#pragma unroll
        for (int e = 0; e < 4; e++) {
            int q = tid + 256 * e;
            int n = q >> 3, kk = q & 7;
            int gn = bn + n, gk = k0 + kk;
            float v = 0.0f;
            if (gk < K && gn < N) v = Bm[(long)gn * ldb + gk];
            Bs[kk][n] = v;
        }
        __syncthreads();
#pragma unroll
        for (int kk = 0; kk < BK; kk++) {
            float4 a4 = *(const float4*)&As[kk][ty * 4];
            float4 b0 = *(const float4*)&Bs[kk][tx * 8];
            float4 b1 = *(const float4*)&Bs[kk][tx * 8 + 4];
            float av[4] = {a4.x, a4.y, a4.z, a4.w};
            float bv[8] = {b0.x, b0.y, b0.z, b0.w, b1.x, b1.y, b1.z, b1.w};
#pragma unroll
            for (int i = 0; i < 4; i++)
#pragma unroll
                for (int j = 0; j < 8; j++)
                    acc[i][j] = fmaf(av[i], bv[j], acc[i][j]);
        }
        __syncthreads();
    }
#pragma unroll
    for (int i = 0; i < 4; i++) {
        int gm = bm + ty * 4 + i;
        if (gm >= M) continue;
#pragma unroll
        for (int j = 0; j < 8; j++) {
            int gn = bn + tx * 8 + j;
            if (gn < N) {
                float v = acc[i][j] + g_bias[gn];
                int g = gn / Hn;
                int rem = gn - g * Hn;
                int r = rem / UPC;
                int nl = rem - r * UPC;
                g_xwp[(long)gm * (NR * JLP) + r * JLP + g * HLP + nl] = v;
            }
        }
    }
}

// ---------------- recurrence: 4-CTA cluster, 2 cluster-syncs per step ----------------
__global__ void __cluster_dims__(NR, 1, 1) __launch_bounds__(RTHREADS)
recurrence_kernel(const float* __restrict__ attv,
                  const float* __restrict__ attWx,
                  const float* __restrict__ context,
                  const int* __restrict__ clen)
{
    extern __shared__ __align__(16) float dynsm[];
    float* s_seqp = dynsm;                  // [SLOC][Hn]
    float* s_ctx  = dynsm + SLOC * Hn;      // [SLOC][Cn]

    int tid = threadIdx.x;
    int lane = tid & 31;
    int wid = tid >> 5;                     // 0..15
    uint32_t r = (uint32_t)(blockIdx.x & (NR - 1));
    int b = blockIdx.x >> 2;

    __shared__ __align__(16) float sh_h[Hn];
    __shared__ __align__(16) float sh_hwx[Hn];
    __shared__ __align__(16) float sh_v[Hn];
    __shared__ __align__(16) float sh_gates[JLP];
    __shared__ __align__(16) float sh_attn[Hn];
    __shared__ __align__(16) float sh_p[SLOC];
    __shared__ __align__(16) float sh_apart[NR][Hn];
    __shared__ float sh_asum[NR];
    __shared__ float sh_c[UPC];
    __shared__ __align__(16) float4 sh_part[512];
    __shared__ float red[9];

    if (tid < Hn) { sh_h[tid] = 0.f; sh_v[tid] = attv[tid]; }
    if (tid < UPC) sh_c[tid] = 0.f;
    int len = clen[b];
    const float* seqp_r = g_seqp + ((long)b * Sn + r * SLOC) * Hn;
    const float* ctx_r  = context + ((long)b * Sn + r * SLOC) * Cn;
    const float* Wp_r = g_Wp + (long)r * Hn * JLP;
    const float* WC_r = g_WC + (long)r * Cn * JLP;
    uint32_t loc_apart = smem_u32(sh_apart);
    uint32_t loc_asum = smem_u32(sh_asum);
    uint32_t loc_h = smem_u32(sh_h);

    // stage seqp + ctx slices into smem once (step-invariant)
    {
        const uint4* gs = (const uint4*)seqp_r;
        const uint4* gc = (const uint4*)ctx_r;
        uint4* ds = (uint4*)s_seqp;
        uint4* dc = (uint4*)s_ctx;
        const int NU = SLOC * Hn / 4;   // 5376
        for (int i = tid; i < NU; i += RTHREADS) {
            ds[i] = gs[i];
            dc[i] = gc[i];
        }
    }
    __syncthreads();
    CLUSTER_SYNC();

    for (int t = 0; t < Tn; t++) {
        const float* xwp_row = g_xwp + ((long)((b * Tn + t) * NR + r)) * JLP;

        // ---- phase A: gates = xwp + h@Wp (352 thr); FULL hwx = h@attWx (126 thr) ----
        if (tid < 352) {
            int q = tid >> 3, kc = tid & 7;
            int k0 = kc * 21;
            const float* wb = Wp_r + q * 4;
            float4 acc = make_float4(0.f, 0.f, 0.f, 0.f);
#pragma unroll
            for (int k = k0; k < k0 + 21; k++) {
                float hk = sh_h[k];
                float4 w = *(const float4*)(wb + (long)k * JLP);
                acc.x = fmaf(hk, w.x, acc.x); acc.y = fmaf(hk, w.y, acc.y);
                acc.z = fmaf(hk, w.z, acc.z); acc.w = fmaf(hk, w.w, acc.w);
            }
            sh_part[tid] = acc;
        } else if (tid < 478) {
            int u = tid - 352;
            int q = u / 3, kc = u - (u / 3) * 3;   // q 0..41, kc 0..2
            int k0 = kc * 56;
            const float* wb = attWx + q * 4;
            float4 acc = make_float4(0.f, 0.f, 0.f, 0.f);
#pragma unroll 8
            for (int k = k0; k < k0 + 56; k++) {
                float hk = sh_h[k];
                float4 w = *(const float4*)(wb + (long)k * Hn);
                acc.x = fmaf(hk, w.x, acc.x); acc.y = fmaf(hk, w.y, acc.y);
                acc.z = fmaf(hk, w.z, acc.z); acc.w = fmaf(hk, w.w, acc.w);
            }
            sh_part[tid] = acc;
        }
        __syncthreads();
        if (tid < HLP) {
            float4 s = make_float4(0.f, 0.f, 0.f, 0.f);
#pragma unroll
            for (int e = 0; e < 8; e++) {
                float4 a = sh_part[tid * 8 + e];
                s.x += a.x; s.y += a.y; s.z += a.z; s.w += a.w;
            }
            float4 xw4 = *(const float4*)(xwp_row + tid * 4);
            s.x += xw4.x; s.y += xw4.y; s.z += xw4.z; s.w += xw4.w;
            *(float4*)&sh_gates[tid * 4] = s;
        } else if (tid < HLP + 42) {
            int q = tid - HLP;
            float4 a0 = sh_part[352 + q * 3];
            float4 a1 = sh_part[352 + q * 3 + 1];
            float4 a2 = sh_part[352 + q * 3 + 2];
            float4 s = make_float4(a0.x + a1.x + a2.x, a0.y + a1.y + a2.y,
                                   a0.z + a1.z + a2.z, a0.w + a1.w + a2.w);
            *(float4*)&sh_hwx[q * 4] = s;
        }
        __syncthreads();   // hwx + gates ready locally (no cluster sync needed)

        // ---- phase B: e, p for local 128 s — 16 warps x 8 rows ----
#pragma unroll 4
        for (int i = 0; i < 8; i++) {
            int sl = wid * 8 + i;
            const float4* sp4 = (const float4*)(s_seqp + (long)sl * Hn);
            float p = 0.f;
            {
                float4 sv = sp4[lane];
                float4 hx = *(const float4*)&sh_hwx[lane * 4];
                float4 vv = *(const float4*)&sh_v[lane * 4];
                p = fmaf(vv.x, tanh_fast(hx.x + sv.x), p);
                p = fmaf(vv.y, tanh_fast(hx.y + sv.y), p);
                p = fmaf(vv.z, tanh_fast(hx.z + sv.z), p);
                p = fmaf(vv.w, tanh_fast(hx.w + sv.w), p);
            }
            if (lane < 10) {
                int q = 32 + lane;
                float4 sv = sp4[q];
                float4 hx = *(const float4*)&sh_hwx[q * 4];
                float4 vv = *(const float4*)&sh_v[q * 4];
                p = fmaf(vv.x, tanh_fast(hx.x + sv.x), p);
                p = fmaf(vv.y, tanh_fast(hx.y + sv.y), p);
                p = fmaf(vv.z, tanh_fast(hx.z + sv.z), p);
                p = fmaf(vv.w, tanh_fast(hx.w + sv.w), p);
            }
#pragma unroll
            for (int o = 16; o; o >>= 1) p += __shfl_xor_sync(0xffffffffu, p, o);
            if (lane == 0)
                sh_p[sl] = ((int)(r * SLOC) + sl < len) ? p : -1e9f;
        }
        __syncthreads();
        float lsum = 0.f;
        if (tid < SLOC) {
            float pv = expf(sh_p[tid]);
            sh_p[tid] = pv;
            lsum = pv;
        }
        if (wid < 4) {
#pragma unroll
            for (int o = 16; o; o >>= 1) lsum += __shfl_xor_sync(0xffffffffu, lsum, o);
            if (lane == 0) red[wid] = lsum;
        }
        __syncthreads();
        if (tid == 0) red[8] = red[0] + red[1] + red[2] + red[3];
        __syncthreads();

        // ---- phase C: attn partial — 12 s-chunks of 11 x 42 c-quads ----
        if (tid < 504) {
            int sc = tid / 42, cq = tid - sc * 42;
            int s0 = sc * 11;
            int s1 = s0 + 11; if (s1 > SLOC) s1 = SLOC;
            float4 acc = make_float4(0.f, 0.f, 0.f, 0.f);
            for (int s = s0; s < s1; s++) {
                float w = sh_p[s];
                float4 c4 = *(const float4*)(s_ctx + (long)s * Cn + cq * 4);
                acc.x = fmaf(w, c4.x, acc.x); acc.y = fmaf(w, c4.y, acc.y);
                acc.z = fmaf(w, c4.z, acc.z); acc.w = fmaf(w, c4.w, acc.w);
            }
            sh_part[sc * 42 + cq] = acc;
        }
        __syncthreads();
        if (tid < Hn) {
            int cq = tid >> 2, comp = tid & 3;
            float sum = 0.f;
#pragma unroll
            for (int sc = 0; sc < 12; sc++)
                sum += ((const float*)&sh_part[sc * 42 + cq])[comp];
            uint32_t la = loc_apart + (r * Hn + tid) * 4;
#pragma unroll
            for (uint32_t tr = 0; tr < NR; tr++)
                st_cluster_f32(mapa_u32(la, tr), sum);
        }
        if (tid == 200) {
            uint32_t la = loc_asum + r * 4;
#pragma unroll
            for (uint32_t tr = 0; tr < NR; tr++)
                st_cluster_f32(mapa_u32(la, tr), red[8]);
        }
        CLUSTER_SYNC();   // #1: attn partials + sums everywhere
        if (tid < Hn) {
            float winv = 1.0f / (sh_asum[0] + sh_asum[1] + sh_asum[2] + sh_asum[3]);
            sh_attn[tid] = (sh_apart[0][tid] + sh_apart[1][tid] +
                            sh_apart[2][tid] + sh_apart[3][tid]) * winv;
        }
        __syncthreads();

        // ---- phase D: gates += attn @ WC — 44 quads x 8 c-chunks of 21 ----
        if (tid < 352) {
            int q = tid >> 3, ks = tid & 7;
            int c0 = ks * 21;
            const float* wb = WC_r + q * 4;
            float4 acc = make_float4(0.f, 0.f, 0.f, 0.f);
#pragma unroll
            for (int c = c0; c < c0 + 21; c++) {
                float ac = sh_attn[c];
                float4 w = *(const float4*)(wb + (long)c * JLP);
                acc.x = fmaf(ac, w.x, acc.x); acc.y = fmaf(ac, w.y, acc.y);
                acc.z = fmaf(ac, w.z, acc.z); acc.w = fmaf(ac, w.w, acc.w);
            }
            sh_part[tid] = acc;
        }
        __syncthreads();
        if (tid < HLP) {
            float4 g = *(float4*)&sh_gates[tid * 4];
#pragma unroll
            for (int e = 0; e < 8; e++) {
                float4 a = sh_part[tid * 8 + e];
                g.x += a.x; g.y += a.y; g.z += a.z; g.w += a.w;
            }
            *(float4*)&sh_gates[tid * 4] = g;
        }
        __syncthreads();

        // ---- phase E: cell update for this rank's 42 units, broadcast h ----
        if (tid < UPC) {
            float ig = sigmoidf(sh_gates[tid]);
            float fg = sigmoidf(sh_gates[HLP + tid]);
            float gg = tanhf(sh_gates[2 * HLP + tid]);
            float og = sigmoidf(sh_gates[3 * HLP + tid]);
            float cn = fmaf(fg, sh_c[tid], ig * gg);
            float hn = og * tanhf(cn);
            sh_c[tid] = cn;
            int n = (int)r * UPC + tid;
            g_hs[(long)(b * Tn + t) * Hn + n] = hn;
            uint32_t la = loc_h + n * 4;
#pragma unroll
            for (uint32_t tr = 0; tr < NR; tr++)
                st_cluster_f32(mapa_u32(la, tr), hn);
        }
        CLUSTER_SYNC();   // #2: h ready for next step
    }
}

// ---------------- launch: recurrence is the 4th kernel (ncu capture target) ----------------
extern "C" void kernel_launch(void* const* d_in, const int* in_sizes, int n_in,
                              void* d_out, int out_size) {
    const float* x       = (const float*)d_in[0];
    const float* context = (const float*)d_in[1];
    const int*   clen    = (const int*)  d_in[2];
    const float* W_ih    = (const float*)d_in[3];
    const float* W_hh    = (const float*)d_in[4];
    const float* b_ih    = (const float*)d_in[5];
    const float* b_hh    = (const float*)d_in[6];
    const float* attWx   = (const float*)d_in[7];
    const float* attWs   = (const float*)d_in[8];
    const float* attb    = (const float*)d_in[9];
    const float* attv    = (const float*)d_in[10];
    const float* Wdec    = (const float*)d_in[11];
    float* out = (float*)d_out;

    static int attr_set = 0;
    if (!attr_set) {
        cudaFuncSetAttribute(recurrence_kernel,
                             cudaFuncAttributeMaxDynamicSharedMemorySize,
                             DYNSM_BYTES);
        attr_set = 1;
    }

    // 1) packed weights + combined bias
    prep_kernel<<<(NR * Hn * JLP + 255) / 256, 256>>>(W_hh, W_ih, attWs, b_ih, b_hh);

    // 2) seq_proj = context @ att_Ws + att_b
    {
        dim3 grid((Hn + 127) / 128, (Bn * Sn) / 64);
        gemm_seqproj<<<grid, 256>>>(context, attb);
    }

    // 3) xw GEMM with fused packing (writes g_xwp directly)
    {
        dim3 grid((G4 + 127) / 128, (Bn * Tn) / 64);
        gemm_xw_packed<<<grid, 256>>>(x, W_ih);
    }

    // 4) cluster-parallel recurrence (512 threads, 2 cluster-syncs/step)
    recurrence_kernel<<<Bn * NR, RTHREADS, DYNSM_BYTES>>>(attv, attWx, context, clen);

    // 5) W_dec -> bf16 hi/lo
    conv_B_kernel<<<((long)NPAD * (KP / 8) + 255) / 256, 256>>>(Wdec);

    // 6) hs -> bf16 hi/lo
    conv_A_kernel<<<(Bn * Tn * (KP / 8) + 255) / 256, 256>>>();

    // 7) decode via mma.sync bf16 hi/lo (pipelined + coalesced epilogue)
    {
        dim3 grid(NTILES_N, NTILES_M);
        decode_mma_kernel<<<grid, 256>>>(out);
    }
}

// round 17
// speedup vs baseline: 1.0844x; 1.0844x over previous
#include <cuda_runtime.h>
#include <cuda_bf16.h>
#include <math.h>
#include <stdint.h>

// Problem dims
#define Bn 32
#define Tn 64
#define In 300
#define Hn 168
#define Cn 168
#define Sn 512
#define Vn 50257
#define G4 672      // 4*H
#define ICn 468     // I + C

// Cluster recurrence dims
#define NR 4        // CTAs per batch (cluster size)
#define UPC 42      // hidden units per CTA
#define HLP 44      // padded group width (mult of 4)
#define JLP 176     // 4*HLP packed gate rows per CTA
#define SLOC 128    // Sn / NR
#define RTHREADS 512
#define DYNSM_FLOATS (2 * SLOC * Hn)          // seqp slice + ctx slice
#define DYNSM_BYTES  (DYNSM_FLOATS * 4)       // 172032 B

// Decode GEMM dims
#define KP 176
#define NPAD 50304
#define NTILES_N 393
#define NTILES_M 16
#define KCHUNKS 11

// ---------------- device scratch ----------------
__device__ __align__(16) float g_seqp[Bn * Sn * Hn];
__device__ __align__(16) float g_xwp[Bn * Tn * NR * JLP];   // packed per-rank xw (pads stay 0)
__device__ __align__(16) float g_Wp[NR * Hn * JLP];         // W_hh packed  [r][k][jl]
__device__ __align__(16) float g_WC[NR * Cn * JLP];         // W_ih_ctx packed [r][c][jl]
__device__ __align__(16) float g_Wx[NR * Hn * HLP];         // attWx slice [r][k][nl]
__device__ __align__(16) float g_WsT[Hn * Cn];
__device__ __align__(16) float g_bias[G4];
__device__ __align__(16) float g_hs[Bn * Tn * Hn];
__device__ __align__(16) __nv_bfloat16 g_Ahi[Bn * Tn * KP];
__device__ __align__(16) __nv_bfloat16 g_Alo[Bn * Tn * KP];
__device__ __align__(16) __nv_bfloat16 g_Bhi[(long)NPAD * KP];
__device__ __align__(16) __nv_bfloat16 g_Blo[(long)NPAD * KP];

// ---------------- helpers ----------------
__device__ __forceinline__ float tanh_fast(float x) {
    float y; asm("tanh.approx.f32 %0, %1;" : "=f"(y) : "f"(x)); return y;
}
__device__ __forceinline__ float sigmoidf(float x) { return 1.0f / (1.0f + expf(-x)); }

__device__ __forceinline__ uint32_t smem_u32(const void* p) {
    uint32_t a;
    asm("{ .reg .u64 t; cvta.to.shared.u64 t, %1; cvt.u32.u64 %0, t; }" : "=r"(a) : "l"(p));
    return a;
}
__device__ __forceinline__ uint32_t mapa_u32(uint32_t a, uint32_t rank) {
    uint32_t r;
    asm("mapa.shared::cluster.u32 %0, %1, %2;" : "=r"(r) : "r"(a), "r"(rank));
    return r;
}
__device__ __forceinline__ void st_cluster_f32(uint32_t a, float v) {
    asm volatile("st.shared::cluster.f32 [%0], %1;" :: "r"(a), "f"(v) : "memory");
}
#define CLUSTER_SYNC() do { \
    asm volatile("barrier.cluster.arrive.aligned;" ::: "memory"); \
    asm volatile("barrier.cluster.wait.aligned;" ::: "memory"); } while (0)

__device__ __forceinline__ void ldsm_x4(uint32_t* r, uint32_t addr) {
    asm volatile("ldmatrix.sync.aligned.m8n8.x4.shared.b16 {%0,%1,%2,%3}, [%4];"
                 : "=r"(r[0]), "=r"(r[1]), "=r"(r[2]), "=r"(r[3]) : "r"(addr));
}
__device__ __forceinline__ void mma_bf16(float* c, const uint32_t* a, uint32_t b0, uint32_t b1) {
    asm volatile(
        "mma.sync.aligned.m16n8k16.row.col.f32.bf16.bf16.f32 "
        "{%0,%1,%2,%3}, {%4,%5,%6,%7}, {%8,%9}, {%0,%1,%2,%3};"
        : "+f"(c[0]), "+f"(c[1]), "+f"(c[2]), "+f"(c[3])
        : "r"(a[0]), "r"(a[1]), "r"(a[2]), "r"(a[3]), "r"(b0), "r"(b1));
}

// ---------------- prep: packed weight images + misc ----------------
__global__ void prep_kernel(const float* __restrict__ Whh,
                            const float* __restrict__ Wih,
                            const float* __restrict__ attWs,
                            const float* __restrict__ attWx,
                            const float* __restrict__ bih,
                            const float* __restrict__ bhh) {
    int idx = blockIdx.x * blockDim.x + threadIdx.x;
    if (idx < NR * Hn * JLP) {
        int r = idx / (Hn * JLP);
        int rem = idx % (Hn * JLP);
        int k = rem / JLP, jl = rem % JLP;
        int g = jl / HLP, nl = jl % HLP;
        float wv = 0.f, wc = 0.f;
        if (nl < UPC) {
            int j = g * Hn + UPC * r + nl;
            wv = Whh[j * Hn + k];
            wc = Wih[j * ICn + In + k];
        }
        g_Wp[idx] = wv;
        g_WC[idx] = wc;
    }
    if (idx < NR * Hn * HLP) {
        int r = idx / (Hn * HLP);
        int rem = idx % (Hn * HLP);
        int k = rem / HLP, nl = rem % HLP;
        g_Wx[idx] = (nl < UPC) ? attWx[k * Hn + UPC * r + nl] : 0.f;
    }
    if (idx < Hn * Cn) {
        int a = idx / Cn, c = idx % Cn;
        g_WsT[a * Cn + c] = attWs[c * Hn + a];
    }
    if (idx < G4) g_bias[idx] = bih[idx] + bhh[idx];
}

// ---------------- hi/lo bf16 conversion ----------------
__device__ __forceinline__ void conv_hilo_body(const float* __restrict__ src, int nrows_src,
                                               __nv_bfloat16* __restrict__ hi,
                                               __nv_bfloat16* __restrict__ lo,
                                               int nrows_pad) {
    int idx = blockIdx.x * blockDim.x + threadIdx.x;
    int row = idx / (KP / 8);
    int u = idx % (KP / 8);
    if (row >= nrows_pad) return;
    int c0 = u * 8;
    __nv_bfloat16 h8[8], l8[8];
    if (row < nrows_src && c0 < Hn) {
        const float* sp = src + (long)row * Hn + c0;
#pragma unroll
        for (int e = 0; e < 8; e++) {
            float v = sp[e];
            __nv_bfloat16 h = __float2bfloat16(v);
            h8[e] = h;
            l8[e] = __float2bfloat16(v - __bfloat162float(h));
        }
    } else {
#pragma unroll
        for (int e = 0; e < 8; e++) { h8[e] = __float2bfloat16(0.f); l8[e] = h8[e]; }
    }
    *(uint4*)(hi + (long)row * KP + c0) = *(uint4*)h8;
    *(uint4*)(lo + (long)row * KP + c0) = *(uint4*)l8;
}
__global__ __launch_bounds__(256) void conv_A_kernel() {
    conv_hilo_body(g_hs, Bn * Tn, g_Ahi, g_Alo, Bn * Tn);
}
__global__ __launch_bounds__(256) void conv_B_kernel(const float* __restrict__ Wdec) {
    conv_hilo_body(Wdec, Vn, g_Bhi, g_Blo, NPAD);
}

// ---------------- decode: bf16 hi/lo mma.sync, pipelined loads + coalesced epilogue (R16, kept) ----------------
#define SSTRIDE 24
__global__ __launch_bounds__(256) void decode_mma_kernel(float* __restrict__ out) {
    __shared__ __align__(16) unsigned char smbuf[4 * 128 * SSTRIDE * 2];
    __nv_bfloat16* sAh = (__nv_bfloat16*)smbuf;
    __nv_bfloat16* sAl = sAh + 128 * SSTRIDE;
    __nv_bfloat16* sBh = sAl + 128 * SSTRIDE;
    __nv_bfloat16* sBl = sBh + 128 * SSTRIDE;

    int tid = threadIdx.x;
    int lane = tid & 31;
    int wid = tid >> 5;
    int wm = (wid & 1) * 64;
    int wn = (wid >> 1) * 32;
    int m0 = blockIdx.y * 128;
    int n0 = blockIdx.x * 128;

    float acc[4][4][4];
#pragma unroll
    for (int i = 0; i < 4; i++)
#pragma unroll
        for (int j = 0; j < 4; j++)
#pragma unroll
            for (int e = 0; e < 4; e++) acc[i][j][e] = 0.f;

    int lrow = tid >> 1;
    int lhalf = (tid & 1) * 8;

    uint32_t aAh = smem_u32(sAh + (wm + (lane & 15)) * SSTRIDE + (lane >> 4) * 8);
    uint32_t aAl = smem_u32(sAl + (wm + (lane & 15)) * SSTRIDE + (lane >> 4) * 8);
    int bg = lane >> 3;
    int brow = wn + (bg >> 1) * 8 + (lane & 7);
    int bk = (bg & 1) * 8;
    uint32_t aBh0 = smem_u32(sBh + brow * SSTRIDE + bk);
    uint32_t aBl0 = smem_u32(sBl + brow * SSTRIDE + bk);

    long kaBase = (long)(m0 + lrow) * KP + lhalf;
    long kbBase = (long)(n0 + lrow) * KP + lhalf;

    uint4 vAh = *(const uint4*)(g_Ahi + kaBase);
    uint4 vAl = *(const uint4*)(g_Alo + kaBase);
    uint4 vBh = *(const uint4*)(g_Bhi + kbBase);
    uint4 vBl = *(const uint4*)(g_Blo + kbBase);

    for (int kc = 0; kc < KCHUNKS; kc++) {
        __syncthreads();
        *(uint4*)(sAh + lrow * SSTRIDE + lhalf) = vAh;
        *(uint4*)(sAl + lrow * SSTRIDE + lhalf) = vAl;
        *(uint4*)(sBh + lrow * SSTRIDE + lhalf) = vBh;
        *(uint4*)(sBl + lrow * SSTRIDE + lhalf) = vBl;
        __syncthreads();

        if (kc + 1 < KCHUNKS) {
            long ka = kaBase + (kc + 1) * 16;
            long kb = kbBase + (kc + 1) * 16;
            vAh = *(const uint4*)(g_Ahi + ka);
            vAl = *(const uint4*)(g_Alo + ka);
            vBh = *(const uint4*)(g_Bhi + kb);
            vBl = *(const uint4*)(g_Blo + kb);
        }

        uint32_t ah[4][4], al[4][4], bh[2][4], bl[2][4];
#pragma unroll
        for (int mi = 0; mi < 4; mi++) {
            ldsm_x4(ah[mi], aAh + mi * 16 * (SSTRIDE * 2));
            ldsm_x4(al[mi], aAl + mi * 16 * (SSTRIDE * 2));
        }
#pragma unroll
        for (int g = 0; g < 2; g++) {
            ldsm_x4(bh[g], aBh0 + g * 16 * (SSTRIDE * 2));
            ldsm_x4(bl[g], aBl0 + g * 16 * (SSTRIDE * 2));
        }

#pragma unroll
        for (int mi = 0; mi < 4; mi++) {
#pragma unroll
            for (int ni = 0; ni < 4; ni++) {
                int g = ni >> 1, sub = (ni & 1) * 2;
                mma_bf16(acc[mi][ni], ah[mi], bh[g][sub], bh[g][sub + 1]);
                mma_bf16(acc[mi][ni], ah[mi], bl[g][sub], bl[g][sub + 1]);
            }
        }
#pragma unroll
        for (int mi = 0; mi < 4; mi++) {
#pragma unroll
            for (int ni = 0; ni < 4; ni++) {
                int g = ni >> 1, sub = (ni & 1) * 2;
                mma_bf16(acc[mi][ni], al[mi], bh[g][sub], bh[g][sub + 1]);
            }
        }
    }

    // coalesced epilogue via smem staging
    float* stg = (float*)smbuf;
    __syncthreads();
    int lrow2 = tid >> 7;
    int lcol = tid & 127;
    int gcol = n0 + lcol;
#pragma unroll
    for (int round = 0; round < 4; round++) {
        if (wm == (round >> 1) * 64) {
            int mibase = (round & 1) * 2;
#pragma unroll
            for (int mi2 = 0; mi2 < 2; mi2++) {
                int mi = mibase + mi2;
                int rloc = mi * 16 + (lane >> 2) - (round & 1) * 32;
#pragma unroll
                for (int ni = 0; ni < 4; ni++) {
                    int cc = wn + (lane & 3) * 2 + ni * 8;
                    stg[rloc * 129 + cc]           = acc[mi][ni][0];
                    stg[rloc * 129 + cc + 1]       = acc[mi][ni][1];
                    stg[(rloc + 8) * 129 + cc]     = acc[mi][ni][2];
                    stg[(rloc + 8) * 129 + cc + 1] = acc[mi][ni][3];
                }
            }
        }
        __syncthreads();
        if (gcol < Vn) {
#pragma unroll
            for (int rr = 0; rr < 32; rr += 2) {
                int row = rr + lrow2;
                out[(long)(m0 + round * 32 + row) * Vn + gcol] = stg[row * 129 + lcol];
            }
        }
        __syncthreads();
    }
}

// ---------------- seqproj SGEMM ----------------
__global__ __launch_bounds__(256) void gemm_seqproj(const float* __restrict__ context,
                                                    const float* __restrict__ attb) {
    const int BM = 64, BN = 128, BK = 8;
    const float* A = context; int lda = Cn;
    const float* Bm = g_WsT;  int ldb = Cn;
    float* D = g_seqp;        int ldd = Hn;
    const int M = Bn * Sn, N = Hn, K = Cn;
    __shared__ float As[BK][BM];
    __shared__ float Bs[BK][BN];
    int bm = blockIdx.y * BM, bn = blockIdx.x * BN;
    int tid = threadIdx.x, tx = tid & 15, ty = tid >> 4;
    float acc[4][8];
#pragma unroll
    for (int i = 0; i < 4; i++)
#pragma unroll
        for (int j = 0; j < 8; j++) acc[i][j] = 0.0f;
    for (int k0 = 0; k0 < K; k0 += BK) {
#pragma unroll
        for (int e = 0; e < 2; e++) {
            int q = tid + 256 * e;
            int m = q >> 3, kk = q & 7;
            int gm = bm + m, gk = k0 + kk;
            float v = 0.0f;
            if (gk < K && gm < M) v = A[(long)gm * lda + gk];
            As[kk][m] = v;
        }
#pragma unroll
        for (int e = 0; e < 4; e++) {
            int q = tid + 256 * e;
            int n = q >> 3, kk = q & 7;
            int gn = bn + n, gk = k0 + kk;
            float v = 0.0f;
            if (gk < K && gn < N) v = Bm[(long)gn * ldb + gk];
            Bs[kk][n] = v;
        }
        __syncthreads();
#pragma unroll
        for (int kk = 0; kk < BK; kk++) {
            float4 a4 = *(const float4*)&As[kk][ty * 4];
            float4 b0 = *(const float4*)&Bs[kk][tx * 8];
            float4 b1 = *(const float4*)&Bs[kk][tx * 8 + 4];
            float av[4] = {a4.x, a4.y, a4.z, a4.w};
            float bv[8] = {b0.x, b0.y, b0.z, b0.w, b1.x, b1.y, b1.z, b1.w};
#pragma unroll
            for (int i = 0; i < 4; i++)
#pragma unroll
                for (int j = 0; j < 8; j++)
                    acc[i][j] = fmaf(av[i], bv[j], acc[i][j]);
        }
        __syncthreads();
    }
#pragma unroll
    for (int i = 0; i < 4; i++) {
        int gm = bm + ty * 4 + i;
        if (gm >= M) continue;
#pragma unroll
        for (int j = 0; j < 8; j++) {
            int gn = bn + tx * 8 + j;
            if (gn < N) D[(long)gm * ldd + gn] = acc[i][j] + attb[gn];
        }
    }
}

// ---------------- xw GEMM with fused packed epilogue ----------------
__global__ __launch_bounds__(256) void gemm_xw_packed(const float* __restrict__ x,
                                                      const float* __restrict__ Wih) {
    const int BM = 64, BN = 128, BK = 8;
    const float* A = x;      int lda = In;
    const float* Bm = Wih;   int ldb = ICn;
    const int M = Bn * Tn, N = G4, K = In;
    __shared__ float As[BK][BM];
    __shared__ float Bs[BK][BN];
    int bm = blockIdx.y * BM, bn = blockIdx.x * BN;
    int tid = threadIdx.x, tx = tid & 15, ty = tid >> 4;
    float acc[4][8];
#pragma unroll
    for (int i = 0; i < 4; i++)
#pragma unroll
        for (int j = 0; j < 8; j++) acc[i][j] = 0.0f;
    for (int k0 = 0; k0 < K; k0 += BK) {
#pragma unroll
        for (int e = 0; e < 2; e++) {
            int q = tid + 256 * e;
            int m = q >> 3, kk = q & 7;
            int gm = bm + m, gk = k0 + kk;
            float v = 0.0f;
            if (gk < K && gm < M) v = A[(long)gm * lda + gk];
            As[kk][m] = v;
        }
#pragma unroll
        for (int e = 0; e < 4; e++) {
            int q = tid + 256 * e;
            int n = q >> 3, kk = q & 7;
            int gn = bn + n, gk = k0 + kk;
            float v = 0.0f;
            if (gk < K && gn < N) v = Bm[(long)gn * ldb + gk];
            Bs[kk][n] = v;
        }
        __syncthreads();
#pragma unroll
        for (int kk = 0; kk < BK; kk++) {
            float4 a4 = *(const float4*)&As[kk][ty * 4];
            float4 b0 = *(const float4*)&Bs[kk][tx * 8];
            float4 b1 = *(const float4*)&Bs[kk][tx * 8 + 4];
            float av[4] = {a4.x, a4.y, a4.z, a4.w};
            float bv[8] = {b0.x, b0.y, b0.z, b0.w, b1.x, b1.y, b1.z, b1.w};
#pragma unroll
            for (int i = 0; i < 4; i++)
#pragma unroll
                for (int j = 0; j < 8; j++)
                    acc[i][j] = fmaf(av[i], bv[j], acc[i][j]);
        }
        __syncthreads();
    }
#pragma unroll
    for (int i = 0; i < 4; i++) {
        int gm = bm + ty * 4 + i;
        if (gm >= M) continue;
#pragma unroll
        for (int j = 0; j < 8; j++) {
            int gn = bn + tx * 8 + j;
            if (gn < N) {
                float v = acc[i][j] + g_bias[gn];
                int g = gn / Hn;
                int rem = gn - g * Hn;
                int r = rem / UPC;
                int nl = rem - r * UPC;
                g_xwp[(long)gm * (NR * JLP) + r * JLP + g * HLP + nl] = v;
            }
        }
    }
}

// ---------------- recurrence: R15 version (measured 803us) ----------------
__global__ void __cluster_dims__(NR, 1, 1) __launch_bounds__(RTHREADS)
recurrence_kernel(const float* __restrict__ attv,
                  const float* __restrict__ context,
                  const int* __restrict__ clen)
{
    extern __shared__ __align__(16) float dynsm[];
    float* s_seqp = dynsm;                  // [SLOC][Hn]
    float* s_ctx  = dynsm + SLOC * Hn;      // [SLOC][Cn]

    int tid = threadIdx.x;
    int lane = tid & 31;
    int wid = tid >> 5;                     // 0..15
    uint32_t r = (uint32_t)(blockIdx.x & (NR - 1));
    int b = blockIdx.x >> 2;

    __shared__ __align__(16) float sh_h[Hn];
    __shared__ __align__(16) float sh_hwx[Hn];
    __shared__ __align__(16) float sh_v[Hn];
    __shared__ __align__(16) float sh_gates[JLP];
    __shared__ __align__(16) float sh_attn[Hn];
    __shared__ __align__(16) float sh_p[SLOC];
    __shared__ __align__(16) float sh_apart[NR][Hn];
    __shared__ float sh_asum[NR];
    __shared__ float sh_c[UPC];
    __shared__ __align__(16) float4 sh_part[512];
    __shared__ float red[9];

    if (tid < Hn) { sh_h[tid] = 0.f; sh_v[tid] = attv[tid]; }
    if (tid < UPC) sh_c[tid] = 0.f;
    int len = clen[b];
    const float* seqp_r = g_seqp + ((long)b * Sn + r * SLOC) * Hn;
    const float* ctx_r  = context + ((long)b * Sn + r * SLOC) * Cn;
    const float* Wp_r = g_Wp + (long)r * Hn * JLP;
    const float* Wx_r = g_Wx + (long)r * Hn * HLP;
    const float* WC_r = g_WC + (long)r * Cn * JLP;
    uint32_t loc_hwx = smem_u32(sh_hwx);
    uint32_t loc_apart = smem_u32(sh_apart);
    uint32_t loc_asum = smem_u32(sh_asum);
    uint32_t loc_h = smem_u32(sh_h);

    {
        const uint4* gs = (const uint4*)seqp_r;
        const uint4* gc = (const uint4*)ctx_r;
        uint4* ds = (uint4*)s_seqp;
        uint4* dc = (uint4*)s_ctx;
        const int NU = SLOC * Hn / 4;   // 5376
        for (int i = tid; i < NU; i += RTHREADS) {
            ds[i] = gs[i];
            dc[i] = gc[i];
        }
    }
    __syncthreads();
    CLUSTER_SYNC();

    for (int t = 0; t < Tn; t++) {
        const float* xwp_row = g_xwp + ((long)((b * Tn + t) * NR + r)) * JLP;

        // ---- phase A: 55 quads (44 gates + 11 hwx) x 8 k-chunks of 21 ----
        if (tid < 440) {
            int q = tid >> 3, kc = tid & 7;
            int k0 = kc * 21;
            const float* wb;
            int stride;
            if (q < HLP) { wb = Wp_r + q * 4; stride = JLP; }
            else         { wb = Wx_r + (q - HLP) * 4; stride = HLP; }
            float4 acc = make_float4(0.f, 0.f, 0.f, 0.f);
#pragma unroll
            for (int k = k0; k < k0 + 21; k++) {
                float hk = sh_h[k];
                float4 w = *(const float4*)(wb + (long)k * stride);
                acc.x = fmaf(hk, w.x, acc.x); acc.y = fmaf(hk, w.y, acc.y);
                acc.z = fmaf(hk, w.z, acc.z); acc.w = fmaf(hk, w.w, acc.w);
            }
            sh_part[tid] = acc;
        }
        __syncthreads();
        if (tid < 55) {
            float4 s = make_float4(0.f, 0.f, 0.f, 0.f);
#pragma unroll
            for (int e = 0; e < 8; e++) {
                float4 a = sh_part[tid * 8 + e];
                s.x += a.x; s.y += a.y; s.z += a.z; s.w += a.w;
            }
            if (tid < HLP) {
                float4 xw4 = *(const float4*)(xwp_row + tid * 4);
                s.x += xw4.x; s.y += xw4.y; s.z += xw4.z; s.w += xw4.w;
                *(float4*)&sh_gates[tid * 4] = s;
            } else {
                int nl4 = (tid - HLP) * 4;
                float v[4] = {s.x, s.y, s.z, s.w};
#pragma unroll
                for (int e = 0; e < 4; e++) {
                    int nl = nl4 + e;
                    if (nl < UPC) {
                        uint32_t la = loc_hwx + (UPC * r + nl) * 4;
#pragma unroll
                        for (uint32_t tr = 0; tr < NR; tr++)
                            st_cluster_f32(mapa_u32(la, tr), v[e]);
                    }
                }
            }
        }
        CLUSTER_SYNC();   // #1: hwx assembled everywhere

        // ---- phase B: e, p for local 128 s — 16 warps x 8 rows ----
#pragma unroll 4
        for (int i = 0; i < 8; i++) {
            int sl = wid * 8 + i;
            const float4* sp4 = (const float4*)(s_seqp + (long)sl * Hn);
            float p = 0.f;
            {
                float4 sv = sp4[lane];
                float4 hx = *(const float4*)&sh_hwx[lane * 4];
                float4 vv = *(const float4*)&sh_v[lane * 4];
                p = fmaf(vv.x, tanh_fast(hx.x + sv.x), p);
                p = fmaf(vv.y, tanh_fast(hx.y + sv.y), p);
                p = fmaf(vv.z, tanh_fast(hx.z + sv.z), p);
                p = fmaf(vv.w, tanh_fast(hx.w + sv.w), p);
            }
            if (lane < 10) {
                int q = 32 + lane;
                float4 sv = sp4[q];
                float4 hx = *(const float4*)&sh_hwx[q * 4];
                float4 vv = *(const float4*)&sh_v[q * 4];
                p = fmaf(vv.x, tanh_fast(hx.x + sv.x), p);
                p = fmaf(vv.y, tanh_fast(hx.y + sv.y), p);
                p = fmaf(vv.z, tanh_fast(hx.z + sv.z), p);
                p = fmaf(vv.w, tanh_fast(hx.w + sv.w), p);
            }
#pragma unroll
            for (int o = 16; o; o >>= 1) p += __shfl_xor_sync(0xffffffffu, p, o);
            if (lane == 0)
                sh_p[sl] = ((int)(r * SLOC) + sl < len) ? p : -1e9f;
        }
        __syncthreads();
        float lsum = 0.f;
        if (tid < SLOC) {
            float pv = expf(sh_p[tid]);
            sh_p[tid] = pv;
            lsum = pv;
        }
        if (wid < 4) {
#pragma unroll
            for (int o = 16; o; o >>= 1) lsum += __shfl_xor_sync(0xffffffffu, lsum, o);
            if (lane == 0) red[wid] = lsum;
        }
        __syncthreads();
        if (tid == 0) red[8] = red[0] + red[1] + red[2] + red[3];
        __syncthreads();

        // ---- phase C: attn partial — 12 s-chunks of 11 x 42 c-quads ----
        if (tid < 504) {
            int sc = tid / 42, cq = tid - sc * 42;
            int s0 = sc * 11;
            int s1 = s0 + 11; if (s1 > SLOC) s1 = SLOC;
            float4 acc = make_float4(0.f, 0.f, 0.f, 0.f);
            for (int s = s0; s < s1; s++) {
                float w = sh_p[s];
                float4 c4 = *(const float4*)(s_ctx + (long)s * Cn + cq * 4);
                acc.x = fmaf(w, c4.x, acc.x); acc.y = fmaf(w, c4.y, acc.y);
                acc.z = fmaf(w, c4.z, acc.z); acc.w = fmaf(w, c4.w, acc.w);
            }
            sh_part[sc * 42 + cq] = acc;
        }
        __syncthreads();
        if (tid < Hn) {
            int cq = tid >> 2, comp = tid & 3;
            float sum = 0.f;
#pragma unroll
            for (int sc = 0; sc < 12; sc++)
                sum += ((const float*)&sh_part[sc * 42 + cq])[comp];
            uint32_t la = loc_apart + (r * Hn + tid) * 4;
#pragma unroll
            for (uint32_t tr = 0; tr < NR; tr++)
                st_cluster_f32(mapa_u32(la, tr), sum);
        }
        if (tid == 200) {
            uint32_t la = loc_asum + r * 4;
#pragma unroll
            for (uint32_t tr = 0; tr < NR; tr++)
                st_cluster_f32(mapa_u32(la, tr), red[8]);
        }
        CLUSTER_SYNC();   // #2: attn partials + sums everywhere
        if (tid < Hn) {
            float winv = 1.0f / (sh_asum[0] + sh_asum[1] + sh_asum[2] + sh_asum[3]);
            sh_attn[tid] = (sh_apart[0][tid] + sh_apart[1][tid] +
                            sh_apart[2][tid] + sh_apart[3][tid]) * winv;
        }
        __syncthreads();

        // ---- phase D: gates += attn @ WC — 44 quads x 8 c-chunks of 21 ----
        if (tid < 352) {
            int q = tid >> 3, ks = tid & 7;
            int c0 = ks * 21;
            const float* wb = WC_r + q * 4;
            float4 acc = make_float4(0.f, 0.f, 0.f, 0.f);
#pragma unroll
            for (int c = c0; c < c0 + 21; c++) {
                float ac = sh_attn[c];
                float4 w = *(const float4*)(wb + (long)c * JLP);
                acc.x = fmaf(ac, w.x, acc.x); acc.y = fmaf(ac, w.y, acc.y);
                acc.z = fmaf(ac, w.z, acc.z); acc.w = fmaf(ac, w.w, acc.w);
            }
            sh_part[tid] = acc;
        }
        __syncthreads();
        if (tid < HLP) {
            float4 g = *(float4*)&sh_gates[tid * 4];
#pragma unroll
            for (int e = 0; e < 8; e++) {
                float4 a = sh_part[tid * 8 + e];
                g.x += a.x; g.y += a.y; g.z += a.z; g.w += a.w;
            }
            *(float4*)&sh_gates[tid * 4] = g;
        }
        __syncthreads();

        // ---- phase E: cell update for this rank's 42 units, broadcast h ----
        if (tid < UPC) {
            float ig = sigmoidf(sh_gates[tid]);
            float fg = sigmoidf(sh_gates[HLP + tid]);
            float gg = tanhf(sh_gates[2 * HLP + tid]);
            float og = sigmoidf(sh_gates[3 * HLP + tid]);
            float cn = fmaf(fg, sh_c[tid], ig * gg);
            float hn = og * tanhf(cn);
            sh_c[tid] = cn;
            int n = (int)r * UPC + tid;
            g_hs[(long)(b * Tn + t) * Hn + n] = hn;
            uint32_t la = loc_h + n * 4;
#pragma unroll
            for (uint32_t tr = 0; tr < NR; tr++)
                st_cluster_f32(mapa_u32(la, tr), hn);
        }
        CLUSTER_SYNC();   // #3: h ready for next step
    }
}

// ---------------- launch ----------------
extern "C" void kernel_launch(void* const* d_in, const int* in_sizes, int n_in,
                              void* d_out, int out_size) {
    const float* x       = (const float*)d_in[0];
    const float* context = (const float*)d_in[1];
    const int*   clen    = (const int*)  d_in[2];
    const float* W_ih    = (const float*)d_in[3];
    const float* W_hh    = (const float*)d_in[4];
    const float* b_ih    = (const float*)d_in[5];
    const float* b_hh    = (const float*)d_in[6];
    const float* attWx   = (const float*)d_in[7];
    const float* attWs   = (const float*)d_in[8];
    const float* attb    = (const float*)d_in[9];
    const float* attv    = (const float*)d_in[10];
    const float* Wdec    = (const float*)d_in[11];
    float* out = (float*)d_out;

    static int attr_set = 0;
    if (!attr_set) {
        cudaFuncSetAttribute(recurrence_kernel,
                             cudaFuncAttributeMaxDynamicSharedMemorySize,
                             DYNSM_BYTES);
        attr_set = 1;
    }

    // 1) packed weights + combined bias
    prep_kernel<<<(NR * Hn * JLP + 255) / 256, 256>>>(W_hh, W_ih, attWs, attWx, b_ih, b_hh);

    // 2) seq_proj = context @ att_Ws + att_b
    {
        dim3 grid((Hn + 127) / 128, (Bn * Sn) / 64);
        gemm_seqproj<<<grid, 256>>>(context, attb);
    }

    // 3) xw GEMM with fused packing
    {
        dim3 grid((G4 + 127) / 128, (Bn * Tn) / 64);
        gemm_xw_packed<<<grid, 256>>>(x, W_ih);
    }

    // 4) cluster-parallel recurrence (R15 version, measured 803us)
    recurrence_kernel<<<Bn * NR, RTHREADS, DYNSM_BYTES>>>(attv, context, clen);

    // 5) W_dec -> bf16 hi/lo
    conv_B_kernel<<<((long)NPAD * (KP / 8) + 255) / 256, 256>>>(Wdec);

    // 6) hs -> bf16 hi/lo
    conv_A_kernel<<<(Bn * Tn * (KP / 8) + 255) / 256, 256>>>();

    // 7) decode via mma.sync bf16 hi/lo (pipelined + coalesced epilogue, measured -60us)
    {
        dim3 grid(NTILES_N, NTILES_M);
        decode_mma_kernel<<<grid, 256>>>(out);
    }
}